// round 13
// baseline (speedup 1.0000x reference)
#include <cuda_runtime.h>
#include <math.h>

#define B_   8192
#define L_   200
#define S_   81
#define SP_  84        /* padded row stride (floats) */
#define CEN_ 40
#define D_   128
#define H_   4
#define XSZ  (L_*S_)   /* 16200 floats per b */

// ---- scratch (device globals; no allocation allowed) ----
__device__ float g_R[(size_t)B_*H_*L_];
__device__ float g_c[(size_t)B_*H_];
__device__ float g_central[(size_t)B_*D_];
__device__ float g_Y[(size_t)B_*H_*L_];
__device__ float g_sur[(size_t)B_*D_];
__device__ float g_dummy;

// 2 no-op launches: ncu capture (4th launch) lands on kmain
__global__ void knop() { if (threadIdx.x == 0) g_dummy = 1.0f; }

// ============================================================
// kprep v3 (R10 measured-best, reverted): 32-b tiles, grid 256,
// block 512. dyn smem = 19968 floats (79872 B)
// ============================================================
__global__ void __launch_bounds__(512, 2) kprep(
    const float* __restrict__ x,  const float* __restrict__ Wk,
    const float* __restrict__ bk, const float* __restrict__ Wv,
    const float* __restrict__ bv, const float* __restrict__ Wq,
    const float* __restrict__ bq)
{
    extern __shared__ float sm[];
    float* XcT = sm;           // [200][32]
    float* Wb  = sm + 6400;    // [256][53]
    const int tid = threadIdx.x;
    const int b0  = blockIdx.x * 32;

    for (int idx = tid; idx < 32 * 200; idx += 512) {
        int bb = idx & 31, l = idx >> 5;
        XcT[l * 32 + bb] = x[(size_t)(b0 + bb) * XSZ + l * S_ + CEN_];
    }
    __syncthreads();

    const int bi = tid & 7;
    const int dj = tid >> 3;
    float acc[4][4];
    #pragma unroll
    for (int v = 0; v < 4; v++)
        #pragma unroll
        for (int u = 0; u < 4; u++) acc[v][u] = 0.f;

    const int w = tid >> 5, lane = tid & 31;
    for (int k0 = 0; k0 < 200; k0 += 50) {
        for (int r = 0; r < 16; r++) {
            int dd = w * 16 + r;
            const float* wr = (dd < 128) ? (Wq + dd * L_) : (Wv + (size_t)(dd - 128) * L_);
            Wb[dd * 53 + lane] = wr[k0 + lane];
            if (lane < 18) Wb[dd * 53 + 32 + lane] = wr[k0 + 32 + lane];
        }
        __syncthreads();
        #pragma unroll 2
        for (int kk = 0; kk < 50; kk++) {
            float4 xa0 = *(const float4*)&XcT[(k0 + kk) * 32 + bi * 4];
            float xa[4] = {xa0.x, xa0.y, xa0.z, xa0.w};
            float wv4[4];
            #pragma unroll
            for (int u = 0; u < 4; u++) wv4[u] = Wb[(dj * 4 + u) * 53 + kk];
            #pragma unroll
            for (int v = 0; v < 4; v++)
                #pragma unroll
                for (int u = 0; u < 4; u++)
                    acc[v][u] += xa[v] * wv4[u];
        }
        __syncthreads();
    }

    float* QT = sm;  // [128][32]
    if (dj < 32) {
        #pragma unroll
        for (int u = 0; u < 4; u++) {
            int d = dj * 4 + u;
            float bqd = bq[d];
            #pragma unroll
            for (int v = 0; v < 4; v++)
                QT[d * 32 + bi * 4 + v] = acc[v][u] + bqd;
        }
    } else {
        #pragma unroll
        for (int u = 0; u < 4; u++) {
            int d = (dj - 32) * 4 + u;
            float bvd = bv[d];
            #pragma unroll
            for (int v = 0; v < 4; v++)
                g_central[(size_t)(b0 + bi * 4 + v) * D_ + d] = acc[v][u] + bvd;
        }
    }
    __syncthreads();

    if (tid < 128) {
        int bb = tid & 31, h = tid >> 5;
        float cacc = 0.f;
        for (int dd = 0; dd < 32; dd++)
            cacc += QT[(h * 32 + dd) * 32 + bb] * bk[h * 32 + dd];
        g_c[(size_t)(b0 + bb) * H_ + h] = cacc;
    }

    float* Wkc = sm + 4096;    // [128][100]
    const int bg = w >> 2;
    const int h  = w & 3;
    for (int lc = 0; lc < 2; lc++) {
        __syncthreads();
        for (int idx = tid; idx < 12800; idx += 512) {
            int dd = idx / 100, ll = idx - dd * 100;
            Wkc[idx] = Wk[(size_t)dd * L_ + lc * 100 + ll];
        }
        __syncthreads();
        {
            float acc2[8][4];
            #pragma unroll
            for (int v = 0; v < 8; v++)
                #pragma unroll
                for (int jj = 0; jj < 4; jj++) acc2[v][jj] = 0.f;
            for (int d = 0; d < 32; d++) {
                float4 q0 = *(const float4*)&QT[(h * 32 + d) * 32 + bg * 8];
                float4 q1 = *(const float4*)&QT[(h * 32 + d) * 32 + bg * 8 + 4];
                float q8[8] = {q0.x, q0.y, q0.z, q0.w, q1.x, q1.y, q1.z, q1.w};
                float wk4[4];
                #pragma unroll
                for (int jj = 0; jj < 4; jj++) {
                    int ll = lane + 32 * jj;
                    wk4[jj] = (ll < 100) ? Wkc[(h * 32 + d) * 100 + ll] : 0.f;
                }
                #pragma unroll
                for (int v = 0; v < 8; v++)
                    #pragma unroll
                    for (int jj = 0; jj < 4; jj++)
                        acc2[v][jj] += q8[v] * wk4[jj];
            }
            #pragma unroll
            for (int jj = 0; jj < 4; jj++) {
                int ll = lane + 32 * jj;
                if (ll < 100) {
                    int l = lc * 100 + ll;
                    #pragma unroll
                    for (int v = 0; v < 8; v++)
                        g_R[(size_t)(b0 + bg * 8 + v) * (H_ * L_) + h * L_ + l] = acc2[v][jj];
                }
            }
        }
    }
}

// ============================================================
// kmain v9: warp-specialized pipeline. 96 scorers + 288 loaders;
// x streams in 4 chunks of 50 rows; scores(chunk t) overlaps
// load(chunk t+1). block 384, 3 CTAs/SM, smem 71760 B.
// ============================================================
__global__ void __launch_bounds__(384, 3) kmain(const float* __restrict__ x)
{
    extern __shared__ float sm[];
    float* xs = sm;            // [200][84]
    float* Rs = sm + 16800;    // [4][200]
    float* cs = Rs + 800;      // [4]
    float* sc = cs + 4;        // [4][84]
    const int tid = threadIdx.x;
    const size_t b = blockIdx.x;
    const float* xb = x + b * XSZ;

    const int q = tid - 96;              // loader id (0..287) when tid>=96
    // loader start indices within a 50-row chunk (4050 elements)
    int l0q = 0, s0q = 0;
    if (tid >= 96) { l0q = q / 81; s0q = q - l0q * 81; }

    // ---- pre-stage: loaders fetch chunk 0; scorers fetch Rs, cs ----
    if (tid >= 96) {
        // chunk 0: rows [0,50)
        int l = l0q, s = s0q;
        #pragma unroll
        for (int k = 0; k < 15; k++) {
            if (k < 14 || q < 18)
                xs[l * SP_ + s] = xb[q + 288 * k];
            s += 45; l += 3;
            if (s >= 81) { s -= 81; l += 1; }
        }
        if (q < 150) {
            int r = q / 3, cc = q - 3 * r;
            xs[r * SP_ + 81 + cc] = 0.f;
        }
    } else {
        for (int i = tid; i < 800; i += 96)
            Rs[i] = g_R[b * 800 + i];
        if (tid < 4) cs[tid] = g_c[b * 4 + tid];
    }
    __syncthreads();

    // ---- pipelined stages: scorers on chunk t, loaders on chunk t+1 ----
    const int sq = tid >> 2;
    const int c  = tid & 3;
    const int s4r = (sq < 21) ? sq * 4 : 76;     // dummies read valid col 76
    // per-c row offsets within a chunk: residues 21*off mod 8 = {0,4,2,6}
    const int OFF0[4] = {0, 12, 26, 38};
    const int CNT[4]  = {12, 14, 12, 12};
    float a[H_][4];
    #pragma unroll
    for (int h = 0; h < H_; h++)
        #pragma unroll
        for (int j = 0; j < 4; j++) a[h][j] = 0.f;

    #pragma unroll
    for (int t = 0; t < 4; t++) {
        if (tid < 96) {
            const int o   = OFF0[c];
            const int cnt = CNT[c];
            const float* xp = xs + (t * 50 + o) * SP_ + s4r;
            const float* rp = Rs + t * 50 + o;
            #pragma unroll 7
            for (int j = 0; j < cnt; j++) {
                float4 xv = *(const float4*)xp;
                float r0 = rp[0], r1 = rp[200], r2 = rp[400], r3 = rp[600];
                a[0][0] += r0 * xv.x; a[0][1] += r0 * xv.y; a[0][2] += r0 * xv.z; a[0][3] += r0 * xv.w;
                a[1][0] += r1 * xv.x; a[1][1] += r1 * xv.y; a[1][2] += r1 * xv.z; a[1][3] += r1 * xv.w;
                a[2][0] += r2 * xv.x; a[2][1] += r2 * xv.y; a[2][2] += r2 * xv.z; a[2][3] += r2 * xv.w;
                a[3][0] += r3 * xv.x; a[3][1] += r3 * xv.y; a[3][2] += r3 * xv.z; a[3][3] += r3 * xv.w;
                xp += SP_; rp += 1;
            }
        } else if (t < 3) {
            const int base = (t + 1) * 50;
            const float* xg = xb + base * 81;
            float* xr = xs + base * SP_;
            int l = l0q, s = s0q;
            #pragma unroll
            for (int k = 0; k < 15; k++) {
                if (k < 14 || q < 18)
                    xr[l * SP_ + s] = xg[q + 288 * k];
                s += 45; l += 3;
                if (s >= 81) { s -= 81; l += 1; }
            }
            if (q < 150) {
                int r = q / 3, cc = q - 3 * r;
                xr[r * SP_ + 81 + cc] = 0.f;
            }
        }
        __syncthreads();
    }

    // ---- reduce over c, write scores ----
    if (tid < 96) {
        const unsigned m = 0xffffffffu;
        #pragma unroll
        for (int h = 0; h < H_; h++)
            #pragma unroll
            for (int j = 0; j < 4; j++) {
                a[h][j] += __shfl_xor_sync(m, a[h][j], 1);
                a[h][j] += __shfl_xor_sync(m, a[h][j], 2);
            }
        if (c == 0 && sq < 21) {
            #pragma unroll
            for (int h = 0; h < H_; h++) {
                float ch = cs[h];
                float4 o;
                float* op = (float*)&o;
                #pragma unroll
                for (int j = 0; j < 4; j++) {
                    int s = sq * 4 + j;
                    float v = (a[h][j] + ch) * 0.0883883476483184405f;
                    if (s == CEN_) v += -1000000.0f;
                    if (s >= 81)  v = -INFINITY;
                    op[j] = v;
                }
                *(float4*)&sc[h * SP_ + sq * 4] = o;
            }
        }
    }
    __syncthreads();

    // ---- softmax: warp h handles row h ----
    const int wid = tid >> 5, lane = tid & 31;
    if (wid < 4) {
        float v0 = sc[wid * SP_ + lane];
        float v1 = sc[wid * SP_ + 32 + lane];
        float v2 = (lane < 20) ? sc[wid * SP_ + 64 + lane] : -INFINITY;
        float mx = fmaxf(v0, fmaxf(v1, v2));
        #pragma unroll
        for (int o = 16; o > 0; o >>= 1) mx = fmaxf(mx, __shfl_xor_sync(0xffffffffu, mx, o));
        float e0 = __expf(v0 - mx), e1 = __expf(v1 - mx);
        float e2 = (lane < 20 && v2 > -INFINITY) ? __expf(v2 - mx) : 0.f;
        float s3 = e0 + e1 + e2;
        #pragma unroll
        for (int o = 16; o > 0; o >>= 1) s3 += __shfl_xor_sync(0xffffffffu, s3, o);
        float rs = 1.f / s3;
        sc[wid * SP_ + lane] = e0 * rs;
        sc[wid * SP_ + 32 + lane] = e1 * rs;
        if (lane < 20) sc[wid * SP_ + 64 + lane] = e2 * rs;
    }
    __syncthreads();

    // ---- y: thread = l, all 4 heads; xs row read exactly once ----
    if (tid < 200) {
        const float* xr = xs + tid * SP_;
        float a0 = 0.f, a1 = 0.f, a2 = 0.f, a3 = 0.f;
        #pragma unroll 7
        for (int c2 = 0; c2 < 21; c2++) {
            float4 xv = *(const float4*)&xr[c2 * 4];
            float4 t0 = *(const float4*)&sc[0 * SP_ + c2 * 4];
            float4 t1 = *(const float4*)&sc[1 * SP_ + c2 * 4];
            float4 t2 = *(const float4*)&sc[2 * SP_ + c2 * 4];
            float4 t3 = *(const float4*)&sc[3 * SP_ + c2 * 4];
            a0 += t0.x * xv.x + t0.y * xv.y + t0.z * xv.z + t0.w * xv.w;
            a1 += t1.x * xv.x + t1.y * xv.y + t1.z * xv.z + t1.w * xv.w;
            a2 += t2.x * xv.x + t2.y * xv.y + t2.z * xv.z + t2.w * xv.w;
            a3 += t3.x * xv.x + t3.y * xv.y + t3.z * xv.z + t3.w * xv.w;
        }
        float* Yb = g_Y + b * 800;
        Yb[tid] = a0; Yb[200 + tid] = a1; Yb[400 + tid] = a2; Yb[600 + tid] = a3;
    }
}

// ============================================================
// ksur v3 (unchanged): grid (256,4), 4 b per warp interleaved.
// block 256, dyn smem = 25728 B
// ============================================================
__global__ void __launch_bounds__(256) ksur(const float* __restrict__ Wv,
                                            const float* __restrict__ bv)
{
    extern __shared__ float sm[];
    float* Wvs = sm;            // [32][201]
    const int tid = threadIdx.x;
    const int b0 = blockIdx.x * 32;
    const int h  = blockIdx.y;
    const int lane = tid & 31, w = tid >> 5;

    for (int idx = tid; idx < 32 * 200; idx += 256) {
        int dd = idx / 200, ll = idx - dd * 200;
        Wvs[dd * 201 + ll] = Wv[(size_t)(h * 32 + dd) * L_ + ll];
    }
    __syncthreads();

    const float* wrow = Wvs + lane * 201;
    const float bvd = bv[h * 32 + lane];
    const unsigned m = 0xffffffffu;

    float yr[4][7];
    #pragma unroll
    for (int i = 0; i < 4; i++) {
        const float* yp = g_Y + (size_t)(b0 + i * 8 + w) * 800 + h * 200;
        #pragma unroll
        for (int t = 0; t < 6; t++) yr[i][t] = yp[lane + 32 * t];
        yr[i][6] = (lane < 8) ? yp[192 + lane] : 0.f;
    }

    float acc[4] = {0.f, 0.f, 0.f, 0.f};
    #pragma unroll
    for (int t = 0; t < 6; t++) {
        #pragma unroll
        for (int j = 0; j < 32; j++) {
            float wv = wrow[t * 32 + j];
            acc[0] += wv * __shfl_sync(m, yr[0][t], j);
            acc[1] += wv * __shfl_sync(m, yr[1][t], j);
            acc[2] += wv * __shfl_sync(m, yr[2][t], j);
            acc[3] += wv * __shfl_sync(m, yr[3][t], j);
        }
    }
    #pragma unroll
    for (int j = 0; j < 8; j++) {
        float wv = wrow[192 + j];
        acc[0] += wv * __shfl_sync(m, yr[0][6], j);
        acc[1] += wv * __shfl_sync(m, yr[1][6], j);
        acc[2] += wv * __shfl_sync(m, yr[2][6], j);
        acc[3] += wv * __shfl_sync(m, yr[3][6], j);
    }

    #pragma unroll
    for (int i = 0; i < 4; i++)
        g_sur[(size_t)(b0 + i * 8 + w) * D_ + h * 32 + lane] = acc[i] + bvd;
}

// ============================================================
// kgate (unchanged)
// ============================================================
__global__ void __launch_bounds__(256) kgate(const float* __restrict__ Wg,
                                             const float* __restrict__ bg,
                                             float* __restrict__ out)
{
    const int lane = threadIdx.x & 31, w = threadIdx.x >> 5;
    const int b = blockIdx.x * 8 + w;
    float4 c4 = *(const float4*)&g_central[(size_t)b * D_ + lane * 4];
    float4 s4 = *(const float4*)&g_sur[(size_t)b * D_ + lane * 4];
    float4 w4 = *(const float4*)&Wg[lane * 4];
    float dot = (c4.x - s4.x) * w4.x + (c4.y - s4.y) * w4.y +
                (c4.z - s4.z) * w4.z + (c4.w - s4.w) * w4.w;
    #pragma unroll
    for (int o = 16; o > 0; o >>= 1) dot += __shfl_xor_sync(0xffffffffu, dot, o);
    float g = 1.f / (1.f + __expf(-(dot + bg[0])));
    float4 o4;
    o4.x = c4.x + g * s4.x; o4.y = c4.y + g * s4.y;
    o4.z = c4.z + g * s4.z; o4.w = c4.w + g * s4.w;
    *(float4*)&out[(size_t)b * D_ + lane * 4] = o4;
}

extern "C" void kernel_launch(void* const* d_in, const int* in_sizes, int n_in,
                              void* d_out, int out_size)
{
    const float* x  = (const float*)d_in[0];
    const float* Wk = (const float*)d_in[1];
    const float* bk = (const float*)d_in[2];
    const float* Wv = (const float*)d_in[3];
    const float* bv = (const float*)d_in[4];
    const float* Wq = (const float*)d_in[5];
    const float* bq = (const float*)d_in[6];
    const float* Wg = (const float*)d_in[7];
    const float* bg = (const float*)d_in[8];
    float* out = (float*)d_out;

    cudaFuncSetAttribute(kprep, cudaFuncAttributeMaxDynamicSharedMemorySize, 79872);
    cudaFuncSetAttribute(kmain, cudaFuncAttributeMaxDynamicSharedMemorySize, 71760);
    cudaFuncSetAttribute(ksur,  cudaFuncAttributeMaxDynamicSharedMemorySize, 25728);

    // 2 knops: ncu capture (4th launch) lands on kmain
    knop<<<1, 32>>>();
    knop<<<1, 32>>>();
    kprep<<<256, 512, 79872>>>(x, Wk, bk, Wv, bv, Wq, bq);
    kmain<<<8192, 384, 71760>>>(x);
    ksur<<<dim3(256, 4), 256, 25728>>>(Wv, bv);
    kgate<<<1024, 256>>>(Wg, bg, out);
}

// round 15
// speedup vs baseline: 1.1084x; 1.1084x over previous
#include <cuda_runtime.h>
#include <math.h>

#define B_   8192
#define L_   200
#define S_   81
#define SP_  84        /* padded row stride (floats) */
#define CEN_ 40
#define D_   128
#define H_   4
#define XSZ  (L_*S_)   /* 16200 floats per b */

typedef unsigned int u32;

// ---- scratch (device globals; no allocation allowed) ----
__device__ float g_R[(size_t)B_*H_*L_];
__device__ float g_c[(size_t)B_*H_];
__device__ float g_central[(size_t)B_*D_];
__device__ float g_Y[(size_t)B_*H_*L_];
__device__ float g_sur[(size_t)B_*D_];
__device__ float g_dummy;

// 1 no-op launch: ncu capture (4th launch) lands on kmain
__global__ void knop() { if (threadIdx.x == 0) g_dummy = 1.0f; }

__device__ __forceinline__ void cp_async4(u32 smem_addr, const float* gptr) {
    asm volatile("cp.async.ca.shared.global [%0], [%1], 4;"
                 :: "r"(smem_addr), "l"(gptr) : "memory");
}

// ============================================================
// kprep v3 (R10/R11 measured-best): 32-b tiles, grid 256, block 512.
// dyn smem = 19968 floats (79872 B)
// ============================================================
__global__ void __launch_bounds__(512, 2) kprep(
    const float* __restrict__ x,  const float* __restrict__ Wk,
    const float* __restrict__ bk, const float* __restrict__ Wv,
    const float* __restrict__ bv, const float* __restrict__ Wq,
    const float* __restrict__ bq)
{
    extern __shared__ float sm[];
    float* XcT = sm;           // [200][32]
    float* Wb  = sm + 6400;    // [256][53]
    const int tid = threadIdx.x;
    const int b0  = blockIdx.x * 32;

    for (int idx = tid; idx < 32 * 200; idx += 512) {
        int bb = idx & 31, l = idx >> 5;
        XcT[l * 32 + bb] = x[(size_t)(b0 + bb) * XSZ + l * S_ + CEN_];
    }
    __syncthreads();

    const int bi = tid & 7;
    const int dj = tid >> 3;
    float acc[4][4];
    #pragma unroll
    for (int v = 0; v < 4; v++)
        #pragma unroll
        for (int u = 0; u < 4; u++) acc[v][u] = 0.f;

    const int w = tid >> 5, lane = tid & 31;
    for (int k0 = 0; k0 < 200; k0 += 50) {
        for (int r = 0; r < 16; r++) {
            int dd = w * 16 + r;
            const float* wr = (dd < 128) ? (Wq + dd * L_) : (Wv + (size_t)(dd - 128) * L_);
            Wb[dd * 53 + lane] = wr[k0 + lane];
            if (lane < 18) Wb[dd * 53 + 32 + lane] = wr[k0 + 32 + lane];
        }
        __syncthreads();
        #pragma unroll 2
        for (int kk = 0; kk < 50; kk++) {
            float4 xa0 = *(const float4*)&XcT[(k0 + kk) * 32 + bi * 4];
            float xa[4] = {xa0.x, xa0.y, xa0.z, xa0.w};
            float wv4[4];
            #pragma unroll
            for (int u = 0; u < 4; u++) wv4[u] = Wb[(dj * 4 + u) * 53 + kk];
            #pragma unroll
            for (int v = 0; v < 4; v++)
                #pragma unroll
                for (int u = 0; u < 4; u++)
                    acc[v][u] += xa[v] * wv4[u];
        }
        __syncthreads();
    }

    float* QT = sm;  // [128][32]
    if (dj < 32) {
        #pragma unroll
        for (int u = 0; u < 4; u++) {
            int d = dj * 4 + u;
            float bqd = bq[d];
            #pragma unroll
            for (int v = 0; v < 4; v++)
                QT[d * 32 + bi * 4 + v] = acc[v][u] + bqd;
        }
    } else {
        #pragma unroll
        for (int u = 0; u < 4; u++) {
            int d = (dj - 32) * 4 + u;
            float bvd = bv[d];
            #pragma unroll
            for (int v = 0; v < 4; v++)
                g_central[(size_t)(b0 + bi * 4 + v) * D_ + d] = acc[v][u] + bvd;
        }
    }
    __syncthreads();

    if (tid < 128) {
        int bb = tid & 31, h = tid >> 5;
        float cacc = 0.f;
        for (int dd = 0; dd < 32; dd++)
            cacc += QT[(h * 32 + dd) * 32 + bb] * bk[h * 32 + dd];
        g_c[(size_t)(b0 + bb) * H_ + h] = cacc;
    }

    float* Wkc = sm + 4096;    // [128][100]
    const int bg = w >> 2;
    const int h  = w & 3;
    for (int lc = 0; lc < 2; lc++) {
        __syncthreads();
        for (int idx = tid; idx < 12800; idx += 512) {
            int dd = idx / 100, ll = idx - dd * 100;
            Wkc[idx] = Wk[(size_t)dd * L_ + lc * 100 + ll];
        }
        __syncthreads();
        {
            float acc2[8][4];
            #pragma unroll
            for (int v = 0; v < 8; v++)
                #pragma unroll
                for (int jj = 0; jj < 4; jj++) acc2[v][jj] = 0.f;
            for (int d = 0; d < 32; d++) {
                float4 q0 = *(const float4*)&QT[(h * 32 + d) * 32 + bg * 8];
                float4 q1 = *(const float4*)&QT[(h * 32 + d) * 32 + bg * 8 + 4];
                float q8[8] = {q0.x, q0.y, q0.z, q0.w, q1.x, q1.y, q1.z, q1.w};
                float wk4[4];
                #pragma unroll
                for (int jj = 0; jj < 4; jj++) {
                    int ll = lane + 32 * jj;
                    wk4[jj] = (ll < 100) ? Wkc[(h * 32 + d) * 100 + ll] : 0.f;
                }
                #pragma unroll
                for (int v = 0; v < 8; v++)
                    #pragma unroll
                    for (int jj = 0; jj < 4; jj++)
                        acc2[v][jj] += q8[v] * wk4[jj];
            }
            #pragma unroll
            for (int jj = 0; jj < 4; jj++) {
                int ll = lane + 32 * jj;
                if (ll < 100) {
                    int l = lc * 100 + ll;
                    #pragma unroll
                    for (int v = 0; v < 8; v++)
                        g_R[(size_t)(b0 + bg * 8 + v) * (H_ * L_) + h * L_ + l] = acc2[v][jj];
                }
            }
        }
    }
}

// ============================================================
// kmain v10: R7 structure with cp.async x-load (LDGSTS, no RAW
// round-trips). 384 threads, 3 CTAs/SM, smem 71760 B.
// ============================================================
__global__ void __launch_bounds__(384, 3) kmain(const float* __restrict__ x)
{
    extern __shared__ float sm[];
    float* xs = sm;            // [200][84]
    float* Rs = sm + 16800;    // [4][200]
    float* cs = Rs + 800;      // [4]
    float* sc = cs + 4;        // [4][84]
    const int tid = threadIdx.x;
    const size_t b = blockIdx.x;

    // ---- load x[b] via cp.async (lane-consecutive gmem, conflict-free STS) ----
    {
        const float* xg = x + b * XSZ + tid;
        int l = tid / 81;
        int s = tid - l * 81;
        u32 off = (u32)__cvta_generic_to_shared(xs) + 4u * (u32)(l * SP_ + s);
        #pragma unroll 6
        for (int it = 0; it < 42; ++it) {
            cp_async4(off, xg + it * 384);
            s += 60;                      // 384 = 4*81 + 60
            if (s >= 81) { s -= 81; off += 4 * 399; }
            else         {           off += 4 * 396; }
        }
        if (tid < 72) cp_async4(off, xg + 42 * 384);
        asm volatile("cp.async.commit_group;" ::: "memory");

        // overlap: zero row padding, fetch Rs/cs with regular loads
        if (tid < 200) {
            xs[tid * SP_ + 81] = 0.f;
            xs[tid * SP_ + 82] = 0.f;
            xs[tid * SP_ + 83] = 0.f;
        }
        for (int i = tid; i < 800; i += 384)
            Rs[i] = g_R[b * 800 + i];
        if (tid < 4) cs[tid] = g_c[b * 4 + tid];

        asm volatile("cp.async.wait_group 0;" ::: "memory");
    }
    __syncthreads();

    // ---- scores: 3 FULL warps (tid<96): sq=tid>>2, c=tid&3 (50 l each) ----
    if (tid < 96) {
        const int sq = tid >> 2;
        const int c  = tid & 3;
        const int s4 = (sq < 21) ? sq * 4 : 80;
        const float* xp = xs + c * 50 * SP_ + s4;
        const float* r0p = Rs + c * 50;
        float a[H_][4];
        #pragma unroll
        for (int h = 0; h < H_; h++)
            #pragma unroll
            for (int j = 0; j < 4; j++) a[h][j] = 0.f;
        #pragma unroll 5
        for (int l = 0; l < 50; l++) {
            float4 xv = *(const float4*)xp;
            float r0 = r0p[l], r1 = r0p[200 + l], r2 = r0p[400 + l], r3 = r0p[600 + l];
            a[0][0] += r0 * xv.x; a[0][1] += r0 * xv.y; a[0][2] += r0 * xv.z; a[0][3] += r0 * xv.w;
            a[1][0] += r1 * xv.x; a[1][1] += r1 * xv.y; a[1][2] += r1 * xv.z; a[1][3] += r1 * xv.w;
            a[2][0] += r2 * xv.x; a[2][1] += r2 * xv.y; a[2][2] += r2 * xv.z; a[2][3] += r2 * xv.w;
            a[3][0] += r3 * xv.x; a[3][1] += r3 * xv.y; a[3][2] += r3 * xv.z; a[3][3] += r3 * xv.w;
            xp += SP_;
        }
        const unsigned m = 0xffffffffu;
        #pragma unroll
        for (int h = 0; h < H_; h++)
            #pragma unroll
            for (int j = 0; j < 4; j++) {
                a[h][j] += __shfl_xor_sync(m, a[h][j], 1);
                a[h][j] += __shfl_xor_sync(m, a[h][j], 2);
            }
        if (c == 0 && sq < 21) {
            #pragma unroll
            for (int h = 0; h < H_; h++) {
                float ch = cs[h];
                float4 o;
                float* op = (float*)&o;
                #pragma unroll
                for (int j = 0; j < 4; j++) {
                    int s = sq * 4 + j;
                    float v = (a[h][j] + ch) * 0.0883883476483184405f;
                    if (s == CEN_) v += -1000000.0f;
                    if (s >= 81)  v = -INFINITY;
                    op[j] = v;
                }
                *(float4*)&sc[h * SP_ + sq * 4] = o;
            }
        }
    }
    __syncthreads();

    // ---- softmax: warp h handles row h ----
    const int wid = tid >> 5, lane = tid & 31;
    if (wid < 4) {
        float v0 = sc[wid * SP_ + lane];
        float v1 = sc[wid * SP_ + 32 + lane];
        float v2 = (lane < 20) ? sc[wid * SP_ + 64 + lane] : -INFINITY;
        float mx = fmaxf(v0, fmaxf(v1, v2));
        #pragma unroll
        for (int o = 16; o > 0; o >>= 1) mx = fmaxf(mx, __shfl_xor_sync(0xffffffffu, mx, o));
        float e0 = __expf(v0 - mx), e1 = __expf(v1 - mx);
        float e2 = (lane < 20 && v2 > -INFINITY) ? __expf(v2 - mx) : 0.f;
        float s3 = e0 + e1 + e2;
        #pragma unroll
        for (int o = 16; o > 0; o >>= 1) s3 += __shfl_xor_sync(0xffffffffu, s3, o);
        float rs = 1.f / s3;
        sc[wid * SP_ + lane] = e0 * rs;
        sc[wid * SP_ + 32 + lane] = e1 * rs;
        if (lane < 20) sc[wid * SP_ + 64 + lane] = e2 * rs;
    }
    __syncthreads();

    // ---- y: thread = l, all 4 heads; xs row read exactly once ----
    if (tid < 200) {
        const float* xr = xs + tid * SP_;
        float a0 = 0.f, a1 = 0.f, a2 = 0.f, a3 = 0.f;
        #pragma unroll 7
        for (int c = 0; c < 21; c++) {
            float4 xv = *(const float4*)&xr[c * 4];
            float4 t0 = *(const float4*)&sc[0 * SP_ + c * 4];
            float4 t1 = *(const float4*)&sc[1 * SP_ + c * 4];
            float4 t2 = *(const float4*)&sc[2 * SP_ + c * 4];
            float4 t3 = *(const float4*)&sc[3 * SP_ + c * 4];
            a0 += t0.x * xv.x + t0.y * xv.y + t0.z * xv.z + t0.w * xv.w;
            a1 += t1.x * xv.x + t1.y * xv.y + t1.z * xv.z + t1.w * xv.w;
            a2 += t2.x * xv.x + t2.y * xv.y + t2.z * xv.z + t2.w * xv.w;
            a3 += t3.x * xv.x + t3.y * xv.y + t3.z * xv.z + t3.w * xv.w;
        }
        float* Yb = g_Y + b * 800;
        Yb[tid] = a0; Yb[200 + tid] = a1; Yb[400 + tid] = a2; Yb[600 + tid] = a3;
    }
}

// ============================================================
// ksur v3 (unchanged): grid (256,4), 4 b per warp interleaved.
// block 256, dyn smem = 25728 B
// ============================================================
__global__ void __launch_bounds__(256) ksur(const float* __restrict__ Wv,
                                            const float* __restrict__ bv)
{
    extern __shared__ float sm[];
    float* Wvs = sm;            // [32][201]
    const int tid = threadIdx.x;
    const int b0 = blockIdx.x * 32;
    const int h  = blockIdx.y;
    const int lane = tid & 31, w = tid >> 5;

    for (int idx = tid; idx < 32 * 200; idx += 256) {
        int dd = idx / 200, ll = idx - dd * 200;
        Wvs[dd * 201 + ll] = Wv[(size_t)(h * 32 + dd) * L_ + ll];
    }
    __syncthreads();

    const float* wrow = Wvs + lane * 201;
    const float bvd = bv[h * 32 + lane];
    const unsigned m = 0xffffffffu;

    float yr[4][7];
    #pragma unroll
    for (int i = 0; i < 4; i++) {
        const float* yp = g_Y + (size_t)(b0 + i * 8 + w) * 800 + h * 200;
        #pragma unroll
        for (int t = 0; t < 6; t++) yr[i][t] = yp[lane + 32 * t];
        yr[i][6] = (lane < 8) ? yp[192 + lane] : 0.f;
    }

    float acc[4] = {0.f, 0.f, 0.f, 0.f};
    #pragma unroll
    for (int t = 0; t < 6; t++) {
        #pragma unroll
        for (int j = 0; j < 32; j++) {
            float wv = wrow[t * 32 + j];
            acc[0] += wv * __shfl_sync(m, yr[0][t], j);
            acc[1] += wv * __shfl_sync(m, yr[1][t], j);
            acc[2] += wv * __shfl_sync(m, yr[2][t], j);
            acc[3] += wv * __shfl_sync(m, yr[3][t], j);
        }
    }
    #pragma unroll
    for (int j = 0; j < 8; j++) {
        float wv = wrow[192 + j];
        acc[0] += wv * __shfl_sync(m, yr[0][6], j);
        acc[1] += wv * __shfl_sync(m, yr[1][6], j);
        acc[2] += wv * __shfl_sync(m, yr[2][6], j);
        acc[3] += wv * __shfl_sync(m, yr[3][6], j);
    }

    #pragma unroll
    for (int i = 0; i < 4; i++)
        g_sur[(size_t)(b0 + i * 8 + w) * D_ + h * 32 + lane] = acc[i] + bvd;
}

// ============================================================
// kgate (unchanged)
// ============================================================
__global__ void __launch_bounds__(256) kgate(const float* __restrict__ Wg,
                                             const float* __restrict__ bg,
                                             float* __restrict__ out)
{
    const int lane = threadIdx.x & 31, w = threadIdx.x >> 5;
    const int b = blockIdx.x * 8 + w;
    float4 c4 = *(const float4*)&g_central[(size_t)b * D_ + lane * 4];
    float4 s4 = *(const float4*)&g_sur[(size_t)b * D_ + lane * 4];
    float4 w4 = *(const float4*)&Wg[lane * 4];
    float dot = (c4.x - s4.x) * w4.x + (c4.y - s4.y) * w4.y +
                (c4.z - s4.z) * w4.z + (c4.w - s4.w) * w4.w;
    #pragma unroll
    for (int o = 16; o > 0; o >>= 1) dot += __shfl_xor_sync(0xffffffffu, dot, o);
    float g = 1.f / (1.f + __expf(-(dot + bg[0])));
    float4 o4;
    o4.x = c4.x + g * s4.x; o4.y = c4.y + g * s4.y;
    o4.z = c4.z + g * s4.z; o4.w = c4.w + g * s4.w;
    *(float4*)&out[(size_t)b * D_ + lane * 4] = o4;
}

extern "C" void kernel_launch(void* const* d_in, const int* in_sizes, int n_in,
                              void* d_out, int out_size)
{
    const float* x  = (const float*)d_in[0];
    const float* Wk = (const float*)d_in[1];
    const float* bk = (const float*)d_in[2];
    const float* Wv = (const float*)d_in[3];
    const float* bv = (const float*)d_in[4];
    const float* Wq = (const float*)d_in[5];
    const float* bq = (const float*)d_in[6];
    const float* Wg = (const float*)d_in[7];
    const float* bg = (const float*)d_in[8];
    float* out = (float*)d_out;

    cudaFuncSetAttribute(kprep, cudaFuncAttributeMaxDynamicSharedMemorySize, 79872);
    cudaFuncSetAttribute(kmain, cudaFuncAttributeMaxDynamicSharedMemorySize, 71760);
    cudaFuncSetAttribute(ksur,  cudaFuncAttributeMaxDynamicSharedMemorySize, 25728);

    // 1 knop: ncu capture (4th launch) lands on kmain
    knop<<<1, 32>>>();
    kprep<<<256, 512, 79872>>>(x, Wk, bk, Wv, bv, Wq, bq);
    kmain<<<8192, 384, 71760>>>(x);
    ksur<<<dim3(256, 4), 256, 25728>>>(Wv, bv);
    kgate<<<1024, 256>>>(Wg, bg, out);
}

// round 16
// speedup vs baseline: 1.1220x; 1.0123x over previous
#include <cuda_runtime.h>
#include <math.h>

#define B_   8192
#define L_   200
#define S_   81
#define SP_  84        /* padded row stride (floats) */
#define CEN_ 40
#define D_   128
#define H_   4
#define XSZ  (L_*S_)   /* 16200 floats per b */

typedef unsigned int u32;

// ---- scratch (device globals; no allocation allowed) ----
__device__ float g_R[(size_t)B_*H_*L_];
__device__ float g_c[(size_t)B_*H_];
__device__ float g_central[(size_t)B_*D_];
__device__ float g_Y[(size_t)B_*H_*L_];
__device__ float g_sur[(size_t)B_*D_];
__device__ float g_dummy;

// 1 no-op launch (keeps launch schedule identical to R15)
__global__ void knop() { if (threadIdx.x == 0) g_dummy = 1.0f; }

__device__ __forceinline__ void cp_async4(u32 smem_addr, const float* gptr) {
    asm volatile("cp.async.ca.shared.global [%0], [%1], 4;"
                 :: "r"(smem_addr), "l"(gptr) : "memory");
}
__device__ __forceinline__ void cp_commit() {
    asm volatile("cp.async.commit_group;" ::: "memory");
}
__device__ __forceinline__ void cp_wait0() {
    asm volatile("cp.async.wait_group 0;" ::: "memory");
}

// ============================================================
// kprep v5: v3 structure with cp.async on all LDG->STS phases.
// 32-b tiles, grid 256, block 512. dyn smem = 79872 B
// ============================================================
__global__ void __launch_bounds__(512, 2) kprep(
    const float* __restrict__ x,  const float* __restrict__ Wk,
    const float* __restrict__ bk, const float* __restrict__ Wv,
    const float* __restrict__ bv, const float* __restrict__ Wq,
    const float* __restrict__ bq)
{
    extern __shared__ float sm[];
    float* XcT = sm;           // [200][32]
    float* Wb  = sm + 6400;    // [256][53]
    const int tid = threadIdx.x;
    const int b0  = blockIdx.x * 32;
    const u32 smbase = (u32)__cvta_generic_to_shared(sm);

    // phase a: gather xs_center via cp.async (scattered 4B)
    for (int idx = tid; idx < 32 * 200; idx += 512) {
        int bb = idx & 31, l = idx >> 5;
        cp_async4(smbase + 4u * (u32)(l * 32 + bb),
                  x + (size_t)(b0 + bb) * XSZ + l * S_ + CEN_);
    }
    cp_commit();
    cp_wait0();
    __syncthreads();

    const int bi = tid & 7;
    const int dj = tid >> 3;
    float acc[4][4];
    #pragma unroll
    for (int v = 0; v < 4; v++)
        #pragma unroll
        for (int u = 0; u < 4; u++) acc[v][u] = 0.f;

    const int w = tid >> 5, lane = tid & 31;
    const u32 wb_base = smbase + 4u * 6400u;
    for (int k0 = 0; k0 < 200; k0 += 50) {
        for (int r = 0; r < 16; r++) {
            int dd = w * 16 + r;
            const float* wr = (dd < 128) ? (Wq + dd * L_) : (Wv + (size_t)(dd - 128) * L_);
            cp_async4(wb_base + 4u * (u32)(dd * 53 + lane), wr + k0 + lane);
            if (lane < 18)
                cp_async4(wb_base + 4u * (u32)(dd * 53 + 32 + lane), wr + k0 + 32 + lane);
        }
        cp_commit();
        cp_wait0();
        __syncthreads();
        #pragma unroll 2
        for (int kk = 0; kk < 50; kk++) {
            float4 xa0 = *(const float4*)&XcT[(k0 + kk) * 32 + bi * 4];
            float xa[4] = {xa0.x, xa0.y, xa0.z, xa0.w};
            float wv4[4];
            #pragma unroll
            for (int u = 0; u < 4; u++) wv4[u] = Wb[(dj * 4 + u) * 53 + kk];
            #pragma unroll
            for (int v = 0; v < 4; v++)
                #pragma unroll
                for (int u = 0; u < 4; u++)
                    acc[v][u] += xa[v] * wv4[u];
        }
        __syncthreads();
    }

    float* QT = sm;  // [128][32]
    if (dj < 32) {
        #pragma unroll
        for (int u = 0; u < 4; u++) {
            int d = dj * 4 + u;
            float bqd = bq[d];
            #pragma unroll
            for (int v = 0; v < 4; v++)
                QT[d * 32 + bi * 4 + v] = acc[v][u] + bqd;
        }
    } else {
        #pragma unroll
        for (int u = 0; u < 4; u++) {
            int d = (dj - 32) * 4 + u;
            float bvd = bv[d];
            #pragma unroll
            for (int v = 0; v < 4; v++)
                g_central[(size_t)(b0 + bi * 4 + v) * D_ + d] = acc[v][u] + bvd;
        }
    }
    __syncthreads();

    if (tid < 128) {
        int bb = tid & 31, h = tid >> 5;
        float cacc = 0.f;
        for (int dd = 0; dd < 32; dd++)
            cacc += QT[(h * 32 + dd) * 32 + bb] * bk[h * 32 + dd];
        g_c[(size_t)(b0 + bb) * H_ + h] = cacc;
    }

    float* Wkc = sm + 4096;    // [128][100]
    const u32 wkc_base = smbase + 4u * 4096u;
    const int bg = w >> 2;
    const int h  = w & 3;
    for (int lc = 0; lc < 2; lc++) {
        __syncthreads();
        for (int idx = tid; idx < 12800; idx += 512) {
            int dd = idx / 100, ll = idx - dd * 100;
            cp_async4(wkc_base + 4u * (u32)idx, Wk + (size_t)dd * L_ + lc * 100 + ll);
        }
        cp_commit();
        cp_wait0();
        __syncthreads();
        {
            float acc2[8][4];
            #pragma unroll
            for (int v = 0; v < 8; v++)
                #pragma unroll
                for (int jj = 0; jj < 4; jj++) acc2[v][jj] = 0.f;
            for (int d = 0; d < 32; d++) {
                float4 q0 = *(const float4*)&QT[(h * 32 + d) * 32 + bg * 8];
                float4 q1 = *(const float4*)&QT[(h * 32 + d) * 32 + bg * 8 + 4];
                float q8[8] = {q0.x, q0.y, q0.z, q0.w, q1.x, q1.y, q1.z, q1.w};
                float wk4[4];
                #pragma unroll
                for (int jj = 0; jj < 4; jj++) {
                    int ll = lane + 32 * jj;
                    wk4[jj] = (ll < 100) ? Wkc[(h * 32 + d) * 100 + ll] : 0.f;
                }
                #pragma unroll
                for (int v = 0; v < 8; v++)
                    #pragma unroll
                    for (int jj = 0; jj < 4; jj++)
                        acc2[v][jj] += q8[v] * wk4[jj];
            }
            #pragma unroll
            for (int jj = 0; jj < 4; jj++) {
                int ll = lane + 32 * jj;
                if (ll < 100) {
                    int l = lc * 100 + ll;
                    #pragma unroll
                    for (int v = 0; v < 8; v++)
                        g_R[(size_t)(b0 + bg * 8 + v) * (H_ * L_) + h * L_ + l] = acc2[v][jj];
                }
            }
        }
    }
}

// ============================================================
// kmain v10 (R15 measured-best, unchanged): cp.async x-load.
// 384 threads, 3 CTAs/SM, smem 71760 B.
// ============================================================
__global__ void __launch_bounds__(384, 3) kmain(const float* __restrict__ x)
{
    extern __shared__ float sm[];
    float* xs = sm;            // [200][84]
    float* Rs = sm + 16800;    // [4][200]
    float* cs = Rs + 800;      // [4]
    float* sc = cs + 4;        // [4][84]
    const int tid = threadIdx.x;
    const size_t b = blockIdx.x;

    {
        const float* xg = x + b * XSZ + tid;
        int l = tid / 81;
        int s = tid - l * 81;
        u32 off = (u32)__cvta_generic_to_shared(xs) + 4u * (u32)(l * SP_ + s);
        #pragma unroll 6
        for (int it = 0; it < 42; ++it) {
            cp_async4(off, xg + it * 384);
            s += 60;                      // 384 = 4*81 + 60
            if (s >= 81) { s -= 81; off += 4 * 399; }
            else         {           off += 4 * 396; }
        }
        if (tid < 72) cp_async4(off, xg + 42 * 384);
        cp_commit();

        if (tid < 200) {
            xs[tid * SP_ + 81] = 0.f;
            xs[tid * SP_ + 82] = 0.f;
            xs[tid * SP_ + 83] = 0.f;
        }
        for (int i = tid; i < 800; i += 384)
            Rs[i] = g_R[b * 800 + i];
        if (tid < 4) cs[tid] = g_c[b * 4 + tid];

        cp_wait0();
    }
    __syncthreads();

    if (tid < 96) {
        const int sq = tid >> 2;
        const int c  = tid & 3;
        const int s4 = (sq < 21) ? sq * 4 : 80;
        const float* xp = xs + c * 50 * SP_ + s4;
        const float* r0p = Rs + c * 50;
        float a[H_][4];
        #pragma unroll
        for (int h = 0; h < H_; h++)
            #pragma unroll
            for (int j = 0; j < 4; j++) a[h][j] = 0.f;
        #pragma unroll 5
        for (int l = 0; l < 50; l++) {
            float4 xv = *(const float4*)xp;
            float r0 = r0p[l], r1 = r0p[200 + l], r2 = r0p[400 + l], r3 = r0p[600 + l];
            a[0][0] += r0 * xv.x; a[0][1] += r0 * xv.y; a[0][2] += r0 * xv.z; a[0][3] += r0 * xv.w;
            a[1][0] += r1 * xv.x; a[1][1] += r1 * xv.y; a[1][2] += r1 * xv.z; a[1][3] += r1 * xv.w;
            a[2][0] += r2 * xv.x; a[2][1] += r2 * xv.y; a[2][2] += r2 * xv.z; a[2][3] += r2 * xv.w;
            a[3][0] += r3 * xv.x; a[3][1] += r3 * xv.y; a[3][2] += r3 * xv.z; a[3][3] += r3 * xv.w;
            xp += SP_;
        }
        const unsigned m = 0xffffffffu;
        #pragma unroll
        for (int h = 0; h < H_; h++)
            #pragma unroll
            for (int j = 0; j < 4; j++) {
                a[h][j] += __shfl_xor_sync(m, a[h][j], 1);
                a[h][j] += __shfl_xor_sync(m, a[h][j], 2);
            }
        if (c == 0 && sq < 21) {
            #pragma unroll
            for (int h = 0; h < H_; h++) {
                float ch = cs[h];
                float4 o;
                float* op = (float*)&o;
                #pragma unroll
                for (int j = 0; j < 4; j++) {
                    int s = sq * 4 + j;
                    float v = (a[h][j] + ch) * 0.0883883476483184405f;
                    if (s == CEN_) v += -1000000.0f;
                    if (s >= 81)  v = -INFINITY;
                    op[j] = v;
                }
                *(float4*)&sc[h * SP_ + sq * 4] = o;
            }
        }
    }
    __syncthreads();

    const int wid = tid >> 5, lane = tid & 31;
    if (wid < 4) {
        float v0 = sc[wid * SP_ + lane];
        float v1 = sc[wid * SP_ + 32 + lane];
        float v2 = (lane < 20) ? sc[wid * SP_ + 64 + lane] : -INFINITY;
        float mx = fmaxf(v0, fmaxf(v1, v2));
        #pragma unroll
        for (int o = 16; o > 0; o >>= 1) mx = fmaxf(mx, __shfl_xor_sync(0xffffffffu, mx, o));
        float e0 = __expf(v0 - mx), e1 = __expf(v1 - mx);
        float e2 = (lane < 20 && v2 > -INFINITY) ? __expf(v2 - mx) : 0.f;
        float s3 = e0 + e1 + e2;
        #pragma unroll
        for (int o = 16; o > 0; o >>= 1) s3 += __shfl_xor_sync(0xffffffffu, s3, o);
        float rs = 1.f / s3;
        sc[wid * SP_ + lane] = e0 * rs;
        sc[wid * SP_ + 32 + lane] = e1 * rs;
        if (lane < 20) sc[wid * SP_ + 64 + lane] = e2 * rs;
    }
    __syncthreads();

    if (tid < 200) {
        const float* xr = xs + tid * SP_;
        float a0 = 0.f, a1 = 0.f, a2 = 0.f, a3 = 0.f;
        #pragma unroll 7
        for (int c = 0; c < 21; c++) {
            float4 xv = *(const float4*)&xr[c * 4];
            float4 t0 = *(const float4*)&sc[0 * SP_ + c * 4];
            float4 t1 = *(const float4*)&sc[1 * SP_ + c * 4];
            float4 t2 = *(const float4*)&sc[2 * SP_ + c * 4];
            float4 t3 = *(const float4*)&sc[3 * SP_ + c * 4];
            a0 += t0.x * xv.x + t0.y * xv.y + t0.z * xv.z + t0.w * xv.w;
            a1 += t1.x * xv.x + t1.y * xv.y + t1.z * xv.z + t1.w * xv.w;
            a2 += t2.x * xv.x + t2.y * xv.y + t2.z * xv.z + t2.w * xv.w;
            a3 += t3.x * xv.x + t3.y * xv.y + t3.z * xv.z + t3.w * xv.w;
        }
        float* Yb = g_Y + b * 800;
        Yb[tid] = a0; Yb[200 + tid] = a1; Yb[400 + tid] = a2; Yb[600 + tid] = a3;
    }
}

// ============================================================
// ksur v3 (unchanged): grid (256,4), 4 b per warp interleaved.
// block 256, dyn smem = 25728 B
// ============================================================
__global__ void __launch_bounds__(256) ksur(const float* __restrict__ Wv,
                                            const float* __restrict__ bv)
{
    extern __shared__ float sm[];
    float* Wvs = sm;            // [32][201]
    const int tid = threadIdx.x;
    const int b0 = blockIdx.x * 32;
    const int h  = blockIdx.y;
    const int lane = tid & 31, w = tid >> 5;

    for (int idx = tid; idx < 32 * 200; idx += 256) {
        int dd = idx / 200, ll = idx - dd * 200;
        Wvs[dd * 201 + ll] = Wv[(size_t)(h * 32 + dd) * L_ + ll];
    }
    __syncthreads();

    const float* wrow = Wvs + lane * 201;
    const float bvd = bv[h * 32 + lane];
    const unsigned m = 0xffffffffu;

    float yr[4][7];
    #pragma unroll
    for (int i = 0; i < 4; i++) {
        const float* yp = g_Y + (size_t)(b0 + i * 8 + w) * 800 + h * 200;
        #pragma unroll
        for (int t = 0; t < 6; t++) yr[i][t] = yp[lane + 32 * t];
        yr[i][6] = (lane < 8) ? yp[192 + lane] : 0.f;
    }

    float acc[4] = {0.f, 0.f, 0.f, 0.f};
    #pragma unroll
    for (int t = 0; t < 6; t++) {
        #pragma unroll
        for (int j = 0; j < 32; j++) {
            float wv = wrow[t * 32 + j];
            acc[0] += wv * __shfl_sync(m, yr[0][t], j);
            acc[1] += wv * __shfl_sync(m, yr[1][t], j);
            acc[2] += wv * __shfl_sync(m, yr[2][t], j);
            acc[3] += wv * __shfl_sync(m, yr[3][t], j);
        }
    }
    #pragma unroll
    for (int j = 0; j < 8; j++) {
        float wv = wrow[192 + j];
        acc[0] += wv * __shfl_sync(m, yr[0][6], j);
        acc[1] += wv * __shfl_sync(m, yr[1][6], j);
        acc[2] += wv * __shfl_sync(m, yr[2][6], j);
        acc[3] += wv * __shfl_sync(m, yr[3][6], j);
    }

    #pragma unroll
    for (int i = 0; i < 4; i++)
        g_sur[(size_t)(b0 + i * 8 + w) * D_ + h * 32 + lane] = acc[i] + bvd;
}

// ============================================================
// kgate (unchanged)
// ============================================================
__global__ void __launch_bounds__(256) kgate(const float* __restrict__ Wg,
                                             const float* __restrict__ bg,
                                             float* __restrict__ out)
{
    const int lane = threadIdx.x & 31, w = threadIdx.x >> 5;
    const int b = blockIdx.x * 8 + w;
    float4 c4 = *(const float4*)&g_central[(size_t)b * D_ + lane * 4];
    float4 s4 = *(const float4*)&g_sur[(size_t)b * D_ + lane * 4];
    float4 w4 = *(const float4*)&Wg[lane * 4];
    float dot = (c4.x - s4.x) * w4.x + (c4.y - s4.y) * w4.y +
                (c4.z - s4.z) * w4.z + (c4.w - s4.w) * w4.w;
    #pragma unroll
    for (int o = 16; o > 0; o >>= 1) dot += __shfl_xor_sync(0xffffffffu, dot, o);
    float g = 1.f / (1.f + __expf(-(dot + bg[0])));
    float4 o4;
    o4.x = c4.x + g * s4.x; o4.y = c4.y + g * s4.y;
    o4.z = c4.z + g * s4.z; o4.w = c4.w + g * s4.w;
    *(float4*)&out[(size_t)b * D_ + lane * 4] = o4;
}

extern "C" void kernel_launch(void* const* d_in, const int* in_sizes, int n_in,
                              void* d_out, int out_size)
{
    const float* x  = (const float*)d_in[0];
    const float* Wk = (const float*)d_in[1];
    const float* bk = (const float*)d_in[2];
    const float* Wv = (const float*)d_in[3];
    const float* bv = (const float*)d_in[4];
    const float* Wq = (const float*)d_in[5];
    const float* bq = (const float*)d_in[6];
    const float* Wg = (const float*)d_in[7];
    const float* bg = (const float*)d_in[8];
    float* out = (float*)d_out;

    cudaFuncSetAttribute(kprep, cudaFuncAttributeMaxDynamicSharedMemorySize, 79872);
    cudaFuncSetAttribute(kmain, cudaFuncAttributeMaxDynamicSharedMemorySize, 71760);
    cudaFuncSetAttribute(ksur,  cudaFuncAttributeMaxDynamicSharedMemorySize, 25728);

    knop<<<1, 32>>>();
    kprep<<<256, 512, 79872>>>(x, Wk, bk, Wv, bv, Wq, bq);
    kmain<<<8192, 384, 71760>>>(x);
    ksur<<<dim3(256, 4), 256, 25728>>>(Wv, bv);
    kgate<<<1024, 256>>>(Wg, bg, out);
}

// round 17
// speedup vs baseline: 1.1306x; 1.0077x over previous
#include <cuda_runtime.h>
#include <math.h>

#define B_   8192
#define L_   200
#define S_   81
#define SP_  84        /* padded row stride (floats) */
#define CEN_ 40
#define D_   128
#define H_   4
#define XSZ  (L_*S_)   /* 16200 floats per b */

typedef unsigned int u32;

// ---- scratch (device globals; no allocation allowed) ----
__device__ float g_R[(size_t)B_*H_*L_];
__device__ float g_c[(size_t)B_*H_];
__device__ float g_central[(size_t)B_*D_];
__device__ float g_Y[(size_t)B_*H_*L_];
__device__ float g_sur[(size_t)B_*D_];
__device__ float g_dummy;

// 2 no-op launches: ncu capture (4th launch) lands on kmain
__global__ void knop() { if (threadIdx.x == 0) g_dummy = 1.0f; }

__device__ __forceinline__ void cp_async4(u32 smem_addr, const float* gptr) {
    asm volatile("cp.async.ca.shared.global [%0], [%1], 4;"
                 :: "r"(smem_addr), "l"(gptr) : "memory");
}
__device__ __forceinline__ void cp_commit() {
    asm volatile("cp.async.commit_group;" ::: "memory");
}
__device__ __forceinline__ void cp_wait0() {
    asm volatile("cp.async.wait_group 0;" ::: "memory");
}

// ============================================================
// kprep v5 (R16 measured-best): cp.async everywhere.
// 32-b tiles, grid 256, block 512. dyn smem = 79872 B
// ============================================================
__global__ void __launch_bounds__(512, 2) kprep(
    const float* __restrict__ x,  const float* __restrict__ Wk,
    const float* __restrict__ bk, const float* __restrict__ Wv,
    const float* __restrict__ bv, const float* __restrict__ Wq,
    const float* __restrict__ bq)
{
    extern __shared__ float sm[];
    float* XcT = sm;           // [200][32]
    float* Wb  = sm + 6400;    // [256][53]
    const int tid = threadIdx.x;
    const int b0  = blockIdx.x * 32;
    const u32 smbase = (u32)__cvta_generic_to_shared(sm);

    for (int idx = tid; idx < 32 * 200; idx += 512) {
        int bb = idx & 31, l = idx >> 5;
        cp_async4(smbase + 4u * (u32)(l * 32 + bb),
                  x + (size_t)(b0 + bb) * XSZ + l * S_ + CEN_);
    }
    cp_commit();
    cp_wait0();
    __syncthreads();

    const int bi = tid & 7;
    const int dj = tid >> 3;
    float acc[4][4];
    #pragma unroll
    for (int v = 0; v < 4; v++)
        #pragma unroll
        for (int u = 0; u < 4; u++) acc[v][u] = 0.f;

    const int w = tid >> 5, lane = tid & 31;
    const u32 wb_base = smbase + 4u * 6400u;
    for (int k0 = 0; k0 < 200; k0 += 50) {
        for (int r = 0; r < 16; r++) {
            int dd = w * 16 + r;
            const float* wr = (dd < 128) ? (Wq + dd * L_) : (Wv + (size_t)(dd - 128) * L_);
            cp_async4(wb_base + 4u * (u32)(dd * 53 + lane), wr + k0 + lane);
            if (lane < 18)
                cp_async4(wb_base + 4u * (u32)(dd * 53 + 32 + lane), wr + k0 + 32 + lane);
        }
        cp_commit();
        cp_wait0();
        __syncthreads();
        #pragma unroll 2
        for (int kk = 0; kk < 50; kk++) {
            float4 xa0 = *(const float4*)&XcT[(k0 + kk) * 32 + bi * 4];
            float xa[4] = {xa0.x, xa0.y, xa0.z, xa0.w};
            float wv4[4];
            #pragma unroll
            for (int u = 0; u < 4; u++) wv4[u] = Wb[(dj * 4 + u) * 53 + kk];
            #pragma unroll
            for (int v = 0; v < 4; v++)
                #pragma unroll
                for (int u = 0; u < 4; u++)
                    acc[v][u] += xa[v] * wv4[u];
        }
        __syncthreads();
    }

    float* QT = sm;  // [128][32]
    if (dj < 32) {
        #pragma unroll
        for (int u = 0; u < 4; u++) {
            int d = dj * 4 + u;
            float bqd = bq[d];
            #pragma unroll
            for (int v = 0; v < 4; v++)
                QT[d * 32 + bi * 4 + v] = acc[v][u] + bqd;
        }
    } else {
        #pragma unroll
        for (int u = 0; u < 4; u++) {
            int d = (dj - 32) * 4 + u;
            float bvd = bv[d];
            #pragma unroll
            for (int v = 0; v < 4; v++)
                g_central[(size_t)(b0 + bi * 4 + v) * D_ + d] = acc[v][u] + bvd;
        }
    }
    __syncthreads();

    if (tid < 128) {
        int bb = tid & 31, h = tid >> 5;
        float cacc = 0.f;
        for (int dd = 0; dd < 32; dd++)
            cacc += QT[(h * 32 + dd) * 32 + bb] * bk[h * 32 + dd];
        g_c[(size_t)(b0 + bb) * H_ + h] = cacc;
    }

    float* Wkc = sm + 4096;    // [128][100]
    const u32 wkc_base = smbase + 4u * 4096u;
    const int bg = w >> 2;
    const int h  = w & 3;
    for (int lc = 0; lc < 2; lc++) {
        __syncthreads();
        for (int idx = tid; idx < 12800; idx += 512) {
            int dd = idx / 100, ll = idx - dd * 100;
            cp_async4(wkc_base + 4u * (u32)idx, Wk + (size_t)dd * L_ + lc * 100 + ll);
        }
        cp_commit();
        cp_wait0();
        __syncthreads();
        {
            float acc2[8][4];
            #pragma unroll
            for (int v = 0; v < 8; v++)
                #pragma unroll
                for (int jj = 0; jj < 4; jj++) acc2[v][jj] = 0.f;
            for (int d = 0; d < 32; d++) {
                float4 q0 = *(const float4*)&QT[(h * 32 + d) * 32 + bg * 8];
                float4 q1 = *(const float4*)&QT[(h * 32 + d) * 32 + bg * 8 + 4];
                float q8[8] = {q0.x, q0.y, q0.z, q0.w, q1.x, q1.y, q1.z, q1.w};
                float wk4[4];
                #pragma unroll
                for (int jj = 0; jj < 4; jj++) {
                    int ll = lane + 32 * jj;
                    wk4[jj] = (ll < 100) ? Wkc[(h * 32 + d) * 100 + ll] : 0.f;
                }
                #pragma unroll
                for (int v = 0; v < 8; v++)
                    #pragma unroll
                    for (int jj = 0; jj < 4; jj++)
                        acc2[v][jj] += q8[v] * wk4[jj];
            }
            #pragma unroll
            for (int jj = 0; jj < 4; jj++) {
                int ll = lane + 32 * jj;
                if (ll < 100) {
                    int l = lc * 100 + ll;
                    #pragma unroll
                    for (int v = 0; v < 8; v++)
                        g_R[(size_t)(b0 + bg * 8 + v) * (H_ * L_) + h * L_ + l] = acc2[v][jj];
                }
            }
        }
    }
}

// ============================================================
// kmain v11: cp.async x-load + h-interleaved Rs (Rs4[l][4]):
// scores iter = 2 LDS.128 per 16 FMA (was 1 vec + 4 scalar).
// 384 threads, 3 CTAs/SM, smem 71760 B.
// ============================================================
__global__ void __launch_bounds__(384, 3) kmain(const float* __restrict__ x)
{
    extern __shared__ float sm[];
    float* xs  = sm;            // [200][84]
    float* Rs4 = sm + 16800;    // [200][4]  h-interleaved
    float* cs  = Rs4 + 800;     // [4]
    float* sc  = cs + 4;        // [4][84]
    const int tid = threadIdx.x;
    const size_t b = blockIdx.x;

    // ---- load x[b] via cp.async; Rs reordered to [l][4] ----
    {
        const float* xg = x + b * XSZ + tid;
        int l = tid / 81;
        int s = tid - l * 81;
        u32 off = (u32)__cvta_generic_to_shared(xs) + 4u * (u32)(l * SP_ + s);
        #pragma unroll 6
        for (int it = 0; it < 42; ++it) {
            cp_async4(off, xg + it * 384);
            s += 60;                      // 384 = 4*81 + 60
            if (s >= 81) { s -= 81; off += 4 * 399; }
            else         {           off += 4 * 396; }
        }
        if (tid < 72) cp_async4(off, xg + 42 * 384);
        cp_commit();

        if (tid < 200) {
            xs[tid * SP_ + 81] = 0.f;
            xs[tid * SP_ + 82] = 0.f;
            xs[tid * SP_ + 83] = 0.f;
        }
        for (int i = tid; i < 800; i += 384) {
            float v = g_R[b * 800 + i];
            int h = i / 200, l2 = i - h * 200;
            Rs4[l2 * 4 + h] = v;
        }
        if (tid < 4) cs[tid] = g_c[b * 4 + tid];

        cp_wait0();
    }
    __syncthreads();

    // ---- scores: 3 FULL warps (tid<96): sq=tid>>2, c=tid&3 (50 l each) ----
    if (tid < 96) {
        const int sq = tid >> 2;
        const int c  = tid & 3;
        const int s4 = (sq < 21) ? sq * 4 : 80;
        const float* xp = xs + c * 50 * SP_ + s4;
        const float* rp = Rs4 + c * 50 * 4;
        float a[H_][4];
        #pragma unroll
        for (int h = 0; h < H_; h++)
            #pragma unroll
            for (int j = 0; j < 4; j++) a[h][j] = 0.f;
        #pragma unroll 5
        for (int l = 0; l < 50; l++) {
            float4 xv = *(const float4*)xp;
            float4 rv = *(const float4*)rp;
            a[0][0] += rv.x * xv.x; a[0][1] += rv.x * xv.y; a[0][2] += rv.x * xv.z; a[0][3] += rv.x * xv.w;
            a[1][0] += rv.y * xv.x; a[1][1] += rv.y * xv.y; a[1][2] += rv.y * xv.z; a[1][3] += rv.y * xv.w;
            a[2][0] += rv.z * xv.x; a[2][1] += rv.z * xv.y; a[2][2] += rv.z * xv.z; a[2][3] += rv.z * xv.w;
            a[3][0] += rv.w * xv.x; a[3][1] += rv.w * xv.y; a[3][2] += rv.w * xv.z; a[3][3] += rv.w * xv.w;
            xp += SP_; rp += 4;
        }
        const unsigned m = 0xffffffffu;
        #pragma unroll
        for (int h = 0; h < H_; h++)
            #pragma unroll
            for (int j = 0; j < 4; j++) {
                a[h][j] += __shfl_xor_sync(m, a[h][j], 1);
                a[h][j] += __shfl_xor_sync(m, a[h][j], 2);
            }
        if (c == 0 && sq < 21) {
            #pragma unroll
            for (int h = 0; h < H_; h++) {
                float ch = cs[h];
                float4 o;
                float* op = (float*)&o;
                #pragma unroll
                for (int j = 0; j < 4; j++) {
                    int s = sq * 4 + j;
                    float v = (a[h][j] + ch) * 0.0883883476483184405f;
                    if (s == CEN_) v += -1000000.0f;
                    if (s >= 81)  v = -INFINITY;
                    op[j] = v;
                }
                *(float4*)&sc[h * SP_ + sq * 4] = o;
            }
        }
    }
    __syncthreads();

    // ---- softmax: warp h handles row h ----
    const int wid = tid >> 5, lane = tid & 31;
    if (wid < 4) {
        float v0 = sc[wid * SP_ + lane];
        float v1 = sc[wid * SP_ + 32 + lane];
        float v2 = (lane < 20) ? sc[wid * SP_ + 64 + lane] : -INFINITY;
        float mx = fmaxf(v0, fmaxf(v1, v2));
        #pragma unroll
        for (int o = 16; o > 0; o >>= 1) mx = fmaxf(mx, __shfl_xor_sync(0xffffffffu, mx, o));
        float e0 = __expf(v0 - mx), e1 = __expf(v1 - mx);
        float e2 = (lane < 20 && v2 > -INFINITY) ? __expf(v2 - mx) : 0.f;
        float s3 = e0 + e1 + e2;
        #pragma unroll
        for (int o = 16; o > 0; o >>= 1) s3 += __shfl_xor_sync(0xffffffffu, s3, o);
        float rs = 1.f / s3;
        sc[wid * SP_ + lane] = e0 * rs;
        sc[wid * SP_ + 32 + lane] = e1 * rs;
        if (lane < 20) sc[wid * SP_ + 64 + lane] = e2 * rs;
    }
    __syncthreads();

    // ---- y: thread = l, all 4 heads; xs row read exactly once ----
    if (tid < 200) {
        const float* xr = xs + tid * SP_;
        float a0 = 0.f, a1 = 0.f, a2 = 0.f, a3 = 0.f;
        #pragma unroll 7
        for (int c = 0; c < 21; c++) {
            float4 xv = *(const float4*)&xr[c * 4];
            float4 t0 = *(const float4*)&sc[0 * SP_ + c * 4];
            float4 t1 = *(const float4*)&sc[1 * SP_ + c * 4];
            float4 t2 = *(const float4*)&sc[2 * SP_ + c * 4];
            float4 t3 = *(const float4*)&sc[3 * SP_ + c * 4];
            a0 += t0.x * xv.x + t0.y * xv.y + t0.z * xv.z + t0.w * xv.w;
            a1 += t1.x * xv.x + t1.y * xv.y + t1.z * xv.z + t1.w * xv.w;
            a2 += t2.x * xv.x + t2.y * xv.y + t2.z * xv.z + t2.w * xv.w;
            a3 += t3.x * xv.x + t3.y * xv.y + t3.z * xv.z + t3.w * xv.w;
        }
        float* Yb = g_Y + b * 800;
        Yb[tid] = a0; Yb[200 + tid] = a1; Yb[400 + tid] = a2; Yb[600 + tid] = a3;
    }
}

// ============================================================
// ksur v3 (unchanged): grid (256,4), 4 b per warp interleaved.
// block 256, dyn smem = 25728 B
// ============================================================
__global__ void __launch_bounds__(256) ksur(const float* __restrict__ Wv,
                                            const float* __restrict__ bv)
{
    extern __shared__ float sm[];
    float* Wvs = sm;            // [32][201]
    const int tid = threadIdx.x;
    const int b0 = blockIdx.x * 32;
    const int h  = blockIdx.y;
    const int lane = tid & 31, w = tid >> 5;

    for (int idx = tid; idx < 32 * 200; idx += 256) {
        int dd = idx / 200, ll = idx - dd * 200;
        Wvs[dd * 201 + ll] = Wv[(size_t)(h * 32 + dd) * L_ + ll];
    }
    __syncthreads();

    const float* wrow = Wvs + lane * 201;
    const float bvd = bv[h * 32 + lane];
    const unsigned m = 0xffffffffu;

    float yr[4][7];
    #pragma unroll
    for (int i = 0; i < 4; i++) {
        const float* yp = g_Y + (size_t)(b0 + i * 8 + w) * 800 + h * 200;
        #pragma unroll
        for (int t = 0; t < 6; t++) yr[i][t] = yp[lane + 32 * t];
        yr[i][6] = (lane < 8) ? yp[192 + lane] : 0.f;
    }

    float acc[4] = {0.f, 0.f, 0.f, 0.f};
    #pragma unroll
    for (int t = 0; t < 6; t++) {
        #pragma unroll
        for (int j = 0; j < 32; j++) {
            float wv = wrow[t * 32 + j];
            acc[0] += wv * __shfl_sync(m, yr[0][t], j);
            acc[1] += wv * __shfl_sync(m, yr[1][t], j);
            acc[2] += wv * __shfl_sync(m, yr[2][t], j);
            acc[3] += wv * __shfl_sync(m, yr[3][t], j);
        }
    }
    #pragma unroll
    for (int j = 0; j < 8; j++) {
        float wv = wrow[192 + j];
        acc[0] += wv * __shfl_sync(m, yr[0][6], j);
        acc[1] += wv * __shfl_sync(m, yr[1][6], j);
        acc[2] += wv * __shfl_sync(m, yr[2][6], j);
        acc[3] += wv * __shfl_sync(m, yr[3][6], j);
    }

    #pragma unroll
    for (int i = 0; i < 4; i++)
        g_sur[(size_t)(b0 + i * 8 + w) * D_ + h * 32 + lane] = acc[i] + bvd;
}

// ============================================================
// kgate (unchanged)
// ============================================================
__global__ void __launch_bounds__(256) kgate(const float* __restrict__ Wg,
                                             const float* __restrict__ bg,
                                             float* __restrict__ out)
{
    const int lane = threadIdx.x & 31, w = threadIdx.x >> 5;
    const int b = blockIdx.x * 8 + w;
    float4 c4 = *(const float4*)&g_central[(size_t)b * D_ + lane * 4];
    float4 s4 = *(const float4*)&g_sur[(size_t)b * D_ + lane * 4];
    float4 w4 = *(const float4*)&Wg[lane * 4];
    float dot = (c4.x - s4.x) * w4.x + (c4.y - s4.y) * w4.y +
                (c4.z - s4.z) * w4.z + (c4.w - s4.w) * w4.w;
    #pragma unroll
    for (int o = 16; o > 0; o >>= 1) dot += __shfl_xor_sync(0xffffffffu, dot, o);
    float g = 1.f / (1.f + __expf(-(dot + bg[0])));
    float4 o4;
    o4.x = c4.x + g * s4.x; o4.y = c4.y + g * s4.y;
    o4.z = c4.z + g * s4.z; o4.w = c4.w + g * s4.w;
    *(float4*)&out[(size_t)b * D_ + lane * 4] = o4;
}

extern "C" void kernel_launch(void* const* d_in, const int* in_sizes, int n_in,
                              void* d_out, int out_size)
{
    const float* x  = (const float*)d_in[0];
    const float* Wk = (const float*)d_in[1];
    const float* bk = (const float*)d_in[2];
    const float* Wv = (const float*)d_in[3];
    const float* bv = (const float*)d_in[4];
    const float* Wq = (const float*)d_in[5];
    const float* bq = (const float*)d_in[6];
    const float* Wg = (const float*)d_in[7];
    const float* bg = (const float*)d_in[8];
    float* out = (float*)d_out;

    cudaFuncSetAttribute(kprep, cudaFuncAttributeMaxDynamicSharedMemorySize, 79872);
    cudaFuncSetAttribute(kmain, cudaFuncAttributeMaxDynamicSharedMemorySize, 71760);
    cudaFuncSetAttribute(ksur,  cudaFuncAttributeMaxDynamicSharedMemorySize, 25728);

    // 2 knops: ncu capture (4th launch) lands on kmain
    knop<<<1, 32>>>();
    knop<<<1, 32>>>();
    kprep<<<256, 512, 79872>>>(x, Wk, bk, Wv, bv, Wq, bq);
    kmain<<<8192, 384, 71760>>>(x);
    ksur<<<dim3(256, 4), 256, 25728>>>(Wv, bv);
    kgate<<<1024, 256>>>(Wg, bg, out);
}